// round 15
// baseline (speedup 1.0000x reference)
#include <cuda_runtime.h>

typedef unsigned long long u64;
typedef unsigned int u32;

// ---- packed f32x2 helpers (PTX-only; ptxas never auto-fuses) ----
__device__ __forceinline__ u64 pack2(float lo, float hi) {
    u64 r; asm("mov.b64 %0, {%1, %2};" : "=l"(r) : "f"(lo), "f"(hi)); return r;
}
__device__ __forceinline__ void unpack2(u64 v, float& lo, float& hi) {
    asm("mov.b64 {%0, %1}, %2;" : "=f"(lo), "=f"(hi) : "l"(v));
}
__device__ __forceinline__ u64 fma2(u64 a, u64 b, u64 c) {
    u64 d; asm("fma.rn.f32x2 %0, %1, %2, %3;" : "=l"(d) : "l"(a), "l"(b), "l"(c)); return d;
}
// one LDS.128 (broadcast): 4 consecutive floats as two f32x2 pairs
__device__ __forceinline__ void lds2(u32 addr, u64& p0, u64& p1) {
    asm volatile("ld.shared.v2.u64 {%0, %1}, [%2];" : "=l"(p0), "=l"(p1) : "r"(addr));
}
__device__ __forceinline__ u32 smem_u32(const void* p) {
    u32 a; asm("{ .reg .u64 t; cvta.to.shared.u64 t, %1; cvt.u32.u64 %0, t; }" : "=r"(a) : "l"(p));
    return a;
}

// ---- MUFU primitives ----
__device__ __forceinline__ float ex2f(float x) { float r; asm("ex2.approx.f32 %0, %1;" : "=f"(r) : "f"(x)); return r; }
__device__ __forceinline__ float rcpf(float x) { float r; asm("rcp.approx.f32 %0, %1;" : "=f"(r) : "f"(x)); return r; }
__device__ __forceinline__ float tanhf_(float x) { return fmaf(-2.0f, rcpf(1.0f + ex2f(2.8853900817779268f * x)), 1.0f); }

#define TSTEPS 512
#define WARPS_PER_CTA 4
#define ROWS_PER_WARP 2

// One warp per TWO batch rows, FUSED step: row A's accumulation chain, then
// A's MUFU gate chains issue and their latency hides under row B's fma2 chain
// (different pipes); A finishes (c,h,store) mid-B; ONE __syncwarp per fused
// step (covers both ping-pong hazards). Weights gate-major f32x2 k-pairs with
// activation scales pre-folded: 128 regs, shared by both rows.
__global__ void __launch_bounds__(32 * WARPS_PER_CTA, 3)
lstm_kernel(const float* __restrict__ x,
            const float* __restrict__ W_ih,
            const float* __restrict__ W_hh,
            const float* __restrict__ b_ih,
            const float* __restrict__ b_hh,
            const float* __restrict__ W_fc,
            const float* __restrict__ b_fc,
            float* __restrict__ out, int B)
{
    // hbuf[phase][warp][row][unit] : phase stride 1024B, row stride 128B
    __shared__ __align__(16) float hbuf[2][WARPS_PER_CTA][ROWS_PER_WARP][32];
    __shared__ __align__(16) float xsm[WARPS_PER_CTA][ROWS_PER_WARP][32];

    const int wl   = threadIdx.x >> 5;
    const int lane = threadIdx.x & 31;
    const int bA   = (blockIdx.x * WARPS_PER_CTA + wl) * ROWS_PER_WARP;
    const int bB   = bA + 1;
    if (bA >= B) return;

    // sigmoid(a)=rcp(1+ex2(-log2e*a)); tanh(a)=fma(-2, rcp(1+ex2(2*log2e*a)), 1)
    const float SG0 = -1.4426950408889634f;  // i
    const float SG1 = -1.4426950408889634f;  // f
    const float SG2 =  2.8853900817779268f;  // g (tanh)
    const float SG3 = -1.4426950408889634f;  // o

    // ---- weights, gate-major k-pairs (scales folded): 64 u64 = 128 regs ----
    u64 w0[16], w1[16], w2[16], w3[16];
#pragma unroll
    for (int q = 0; q < 16; q++) {
        const float* r0 = W_hh + (lane)      * 32 + 2 * q;
        const float* r1 = W_hh + (32 + lane) * 32 + 2 * q;
        const float* r2 = W_hh + (64 + lane) * 32 + 2 * q;
        const float* r3 = W_hh + (96 + lane) * 32 + 2 * q;
        w0[q] = pack2(SG0 * r0[0], SG0 * r0[1]);
        w1[q] = pack2(SG1 * r1[0], SG1 * r1[1]);
        w2[q] = pack2(SG2 * r2[0], SG2 * r2[1]);
        w3[q] = pack2(SG3 * r3[0], SG3 * r3[1]);
    }
    const float wih0 = SG0 * W_ih[lane],      bia0 = SG0 * (b_ih[lane]      + b_hh[lane]);
    const float wih1 = SG1 * W_ih[32 + lane], bia1 = SG1 * (b_ih[32 + lane] + b_hh[32 + lane]);
    const float wih2 = SG2 * W_ih[64 + lane], bia2 = SG2 * (b_ih[64 + lane] + b_hh[64 + lane]);
    const float wih3 = SG3 * W_ih[96 + lane], bia3 = SG3 * (b_ih[96 + lane] + b_hh[96 + lane]);

    float hA = 0.f, cA = 0.f, hB = 0.f, cB = 0.f;
    hbuf[0][wl][0][lane] = 0.0f;
    hbuf[0][wl][1][lane] = 0.0f;

    // base smem addr of this warp's phase-0 row-A h buffer;
    //   +1024 -> phase 1, +128 -> row B, +lane*4 -> own slot
    const u32 hb = smem_u32(&hbuf[0][wl][0][0]);
    const float* xspA = &xsm[wl][0][0];
    const float* xspB = &xsm[wl][1][0];
    const float* xbA  = x + (size_t)bA * TSTEPS;
    const float* xbB  = x + (size_t)bB * TSTEPS;

// 64-fma2 accumulation chain for one row (reads h pairs at RD)
#define CHAIN(RD, A0, A1, A2, A3)                                              \
        u64 A0 = 0ull, A1 = 0ull, A2 = 0ull, A3 = 0ull;                        \
        _Pragma("unroll")                                                      \
        for (int m = 0; m < 8; m++) {                                          \
            u64 pA_, pB_;                                                      \
            lds2((RD) + m * 16, pA_, pB_);                                     \
            A0 = fma2(w0[2 * m],     pA_, A0);                                 \
            A1 = fma2(w1[2 * m],     pA_, A1);                                 \
            A2 = fma2(w2[2 * m],     pA_, A2);                                 \
            A3 = fma2(w3[2 * m],     pA_, A3);                                 \
            A0 = fma2(w0[2 * m + 1], pB_, A0);                                 \
            A1 = fma2(w1[2 * m + 1], pB_, A1);                                 \
            A2 = fma2(w2[2 * m + 1], pB_, A2);                                 \
            A3 = fma2(w3[2 * m + 1], pB_, A3);                                 \
        }

// FUSED two-row step. Program order hides A's MUFU tail under B's fma2 chain.
#define STEP2(TT, PH_RD, PH_WR)                                                \
    {                                                                          \
        const float xvA = xspA[(TT)];                                          \
        const float xvB = xspB[(TT)];                                          \
        /* ---- row A accumulation ---- */                                     \
        CHAIN((PH_RD), a0, a1, a2, a3)                                         \
        float l0, u0_, l1, u1_, l2, u2_, l3, u3_;                              \
        unpack2(a0, l0, u0_);                                                  \
        unpack2(a1, l1, u1_);                                                  \
        unpack2(a2, l2, u2_);                                                  \
        unpack2(a3, l3, u3_);                                                  \
        const float sA0 = fmaf(xvA, wih0, bia0) + (l0 + u0_);                  \
        const float sA1 = fmaf(xvA, wih1, bia1) + (l1 + u1_);                  \
        const float sA2 = fmaf(xvA, wih2, bia2) + (l2 + u2_);                  \
        const float sA3 = fmaf(xvA, wih3, bia3) + (l3 + u3_);                  \
        /* A's MUFU gate chains issue now; latency hides under B's chain */    \
        const float igA = rcpf(1.0f + ex2f(sA0));                              \
        const float fgA = rcpf(1.0f + ex2f(sA1));                              \
        const float ggA = fmaf(-2.0f, rcpf(1.0f + ex2f(sA2)), 1.0f);           \
        const float ogA = rcpf(1.0f + ex2f(sA3));                              \
        /* ---- row B accumulation (fma pipe; overlaps A's MUFU) ---- */       \
        CHAIN((PH_RD) + 128, b0, b1, b2, b3)                                   \
        /* ---- finish row A ---- */                                           \
        cA = fmaf(fgA, cA, igA * ggA);                                         \
        hA = ogA * tanhf_(cA);                                                 \
        asm volatile("st.shared.f32 [%0], %1;"                                 \
                     :: "r"((PH_WR) + lane * 4), "f"(hA) : "memory");          \
        /* ---- finish row B ---- */                                           \
        float m0, n0_, m1, n1_, m2, n2_, m3, n3_;                              \
        unpack2(b0, m0, n0_);                                                  \
        unpack2(b1, m1, n1_);                                                  \
        unpack2(b2, m2, n2_);                                                  \
        unpack2(b3, m3, n3_);                                                  \
        const float sB0 = fmaf(xvB, wih0, bia0) + (m0 + n0_);                  \
        const float sB1 = fmaf(xvB, wih1, bia1) + (m1 + n1_);                  \
        const float sB2 = fmaf(xvB, wih2, bia2) + (m2 + n2_);                  \
        const float sB3 = fmaf(xvB, wih3, bia3) + (m3 + n3_);                  \
        const float igB = rcpf(1.0f + ex2f(sB0));                              \
        const float fgB = rcpf(1.0f + ex2f(sB1));                              \
        const float ggB = fmaf(-2.0f, rcpf(1.0f + ex2f(sB2)), 1.0f);           \
        const float ogB = rcpf(1.0f + ex2f(sB3));                              \
        cB = fmaf(fgB, cB, igB * ggB);                                         \
        hB = ogB * tanhf_(cB);                                                 \
        asm volatile("st.shared.f32 [%0], %1;"                                 \
                     :: "r"((PH_WR) + 128 + lane * 4), "f"(hB) : "memory");    \
        __syncwarp();   /* single barrier: next-step reads of PH_WR and       \
                           next-step writes of PH_RD both ordered here */      \
    }

#pragma unroll 1
    for (int tc = 0; tc < TSTEPS; tc += 32) {
        xsm[wl][0][lane] = xbA[tc + lane];   // coalesced 128B per warp
        xsm[wl][1][lane] = xbB[tc + lane];
        __syncwarp();

#pragma unroll 1
        for (int tt = 0; tt < 32; tt += 2) {
            STEP2(tt,     hb,        hb + 1024)   // phase 0 -> 1
            STEP2(tt + 1, hb + 1024, hb)          // phase 1 -> 0
        }
    }
#undef STEP2
#undef CHAIN

    // ---- final head: out[b] = dot(h, W_fc) + b_fc ----
    const float wfc = W_fc[lane];
    float pA = hA * wfc, pB = hB * wfc;
#pragma unroll
    for (int off = 16; off; off >>= 1) {
        pA += __shfl_xor_sync(0xffffffffu, pA, off);
        pB += __shfl_xor_sync(0xffffffffu, pB, off);
    }
    if (lane == 0) {
        out[bA] = pA + b_fc[0];
        if (bB < B) out[bB] = pB + b_fc[0];
    }
}

extern "C" void kernel_launch(void* const* d_in, const int* in_sizes, int n_in,
                              void* d_out, int out_size)
{
    const float* x    = (const float*)d_in[0];
    const float* W_ih = (const float*)d_in[1];
    const float* W_hh = (const float*)d_in[2];
    const float* b_ih = (const float*)d_in[3];
    const float* b_hh = (const float*)d_in[4];
    const float* W_fc = (const float*)d_in[5];
    const float* b_fc = (const float*)d_in[6];
    float* out = (float*)d_out;

    int B = in_sizes[0] / TSTEPS;  // x is [B, 512, 1]
    int rows_per_cta = WARPS_PER_CTA * ROWS_PER_WARP;
    int blocks = (B + rows_per_cta - 1) / rows_per_cta;
    lstm_kernel<<<blocks, 32 * WARPS_PER_CTA>>>(x, W_ih, W_hh, b_ih, b_hh, W_fc, b_fc, out, B);
}